// round 1
// baseline (speedup 1.0000x reference)
#include <cuda_runtime.h>

// Problem constants
#define BATCH   2
#define SEQ     2048
#define EMB     1024
#define HEADS   16
#define HDIM    64
#define MTOT    (BATCH*SEQ)        // 4096
#define SCALE   0.125f             // 64^-0.5

// Scratch (device globals: allowed; cudaMalloc is not)
__device__ float g_q[BATCH*HEADS*SEQ*HDIM];
__device__ float g_k[BATCH*HEADS*SEQ*HDIM];
__device__ float g_v[BATCH*HEADS*SEQ*HDIM];
__device__ float g_ctx[MTOT*EMB];

// ---------------------------------------------------------------------------
// GEMM1: qkv = x @ w_qkv^T + b_qkv, scattered into Q/K/V [B,H,N,D] layout.
// 128x128 block tile, BK=8, 256 threads, 8x8 per thread.
// ---------------------------------------------------------------------------
__global__ __launch_bounds__(256) void gemm_qkv_kernel(
    const float* __restrict__ A,     // x [4096,1024]
    const float* __restrict__ W,     // w_qkv [3072,1024]
    const float* __restrict__ bias)  // b_qkv [3072]
{
    __shared__ float As[8][132];
    __shared__ float Bs[8][132];
    const int tid = threadIdx.x;
    const int tx = tid & 15, ty = tid >> 4;
    const int m0 = blockIdx.y * 128, n0 = blockIdx.x * 128;
    const int lr = tid >> 1, lc = (tid & 1) << 2;

    const float* ap = A + (size_t)(m0 + lr) * EMB + lc;
    const float* bp = W + (size_t)(n0 + lr) * EMB + lc;

    float acc[8][8];
#pragma unroll
    for (int i = 0; i < 8; i++)
#pragma unroll
        for (int j = 0; j < 8; j++) acc[i][j] = 0.f;

    for (int k0 = 0; k0 < EMB; k0 += 8) {
        float4 av = *(const float4*)(ap + k0);
        float4 bv = *(const float4*)(bp + k0);
        As[lc+0][lr] = av.x; As[lc+1][lr] = av.y; As[lc+2][lr] = av.z; As[lc+3][lr] = av.w;
        Bs[lc+0][lr] = bv.x; Bs[lc+1][lr] = bv.y; Bs[lc+2][lr] = bv.z; Bs[lc+3][lr] = bv.w;
        __syncthreads();
#pragma unroll
        for (int kk = 0; kk < 8; kk++) {
            float4 a0 = *(float4*)&As[kk][ty*8];
            float4 a1 = *(float4*)&As[kk][ty*8+4];
            float4 b0 = *(float4*)&Bs[kk][tx*8];
            float4 b1 = *(float4*)&Bs[kk][tx*8+4];
            float ar[8] = {a0.x,a0.y,a0.z,a0.w,a1.x,a1.y,a1.z,a1.w};
            float br[8] = {b0.x,b0.y,b0.z,b0.w,b1.x,b1.y,b1.z,b1.w};
#pragma unroll
            for (int i = 0; i < 8; i++)
#pragma unroll
                for (int j = 0; j < 8; j++)
                    acc[i][j] += ar[i] * br[j];
        }
        __syncthreads();
    }

#pragma unroll
    for (int i = 0; i < 8; i++) {
        const int r = m0 + ty*8 + i;
        const int b = r >> 11;          // /2048
        const int n = r & 2047;
#pragma unroll
        for (int j = 0; j < 8; j++) {
            const int c = n0 + tx*8 + j;
            const float val = acc[i][j] + bias[c];
            const int which = c >> 10;
            const int hd = c & 1023;
            const int h = hd >> 6, d = hd & 63;
            float* dst = (which == 0) ? g_q : (which == 1) ? g_k : g_v;
            dst[((((b<<4) + h) * SEQ) + n) * HDIM + d] = val;
        }
    }
}

// ---------------------------------------------------------------------------
// GEMM2: out = ctx @ w_out^T + b_out
// ---------------------------------------------------------------------------
__global__ __launch_bounds__(256) void gemm_out_kernel(
    const float* __restrict__ W,     // w_out [1024,1024]
    const float* __restrict__ bias,  // b_out [1024]
    float* __restrict__ out)         // [4096,1024]
{
    __shared__ float As[8][132];
    __shared__ float Bs[8][132];
    const int tid = threadIdx.x;
    const int tx = tid & 15, ty = tid >> 4;
    const int m0 = blockIdx.y * 128, n0 = blockIdx.x * 128;
    const int lr = tid >> 1, lc = (tid & 1) << 2;

    const float* ap = g_ctx + (size_t)(m0 + lr) * EMB + lc;
    const float* bp = W + (size_t)(n0 + lr) * EMB + lc;

    float acc[8][8];
#pragma unroll
    for (int i = 0; i < 8; i++)
#pragma unroll
        for (int j = 0; j < 8; j++) acc[i][j] = 0.f;

    for (int k0 = 0; k0 < EMB; k0 += 8) {
        float4 av = *(const float4*)(ap + k0);
        float4 bv = *(const float4*)(bp + k0);
        As[lc+0][lr] = av.x; As[lc+1][lr] = av.y; As[lc+2][lr] = av.z; As[lc+3][lr] = av.w;
        Bs[lc+0][lr] = bv.x; Bs[lc+1][lr] = bv.y; Bs[lc+2][lr] = bv.z; Bs[lc+3][lr] = bv.w;
        __syncthreads();
#pragma unroll
        for (int kk = 0; kk < 8; kk++) {
            float4 a0 = *(float4*)&As[kk][ty*8];
            float4 a1 = *(float4*)&As[kk][ty*8+4];
            float4 b0 = *(float4*)&Bs[kk][tx*8];
            float4 b1 = *(float4*)&Bs[kk][tx*8+4];
            float ar[8] = {a0.x,a0.y,a0.z,a0.w,a1.x,a1.y,a1.z,a1.w};
            float br[8] = {b0.x,b0.y,b0.z,b0.w,b1.x,b1.y,b1.z,b1.w};
#pragma unroll
            for (int i = 0; i < 8; i++)
#pragma unroll
                for (int j = 0; j < 8; j++)
                    acc[i][j] += ar[i] * br[j];
        }
        __syncthreads();
    }

#pragma unroll
    for (int i = 0; i < 8; i++) {
        const int r = m0 + ty*8 + i;
        const int cbase = n0 + tx*8;
        float4 o0, o1;
        o0.x = acc[i][0] + bias[cbase+0];
        o0.y = acc[i][1] + bias[cbase+1];
        o0.z = acc[i][2] + bias[cbase+2];
        o0.w = acc[i][3] + bias[cbase+3];
        o1.x = acc[i][4] + bias[cbase+4];
        o1.y = acc[i][5] + bias[cbase+5];
        o1.z = acc[i][6] + bias[cbase+6];
        o1.w = acc[i][7] + bias[cbase+7];
        *(float4*)(out + (size_t)r * EMB + cbase)     = o0;
        *(float4*)(out + (size_t)r * EMB + cbase + 4) = o1;
    }
}

// ---------------------------------------------------------------------------
// Flash attention: grid (B*H, SEQ/64). 64 queries/block, 64-key tiles,
// online softmax. 256 threads = 16x16; each thread owns a 4x4 fragment.
// Smem: Qs (scaled), KP (K^T, aliased by P), Vs => exactly 48KB static.
// ---------------------------------------------------------------------------
__global__ __launch_bounds__(256) void attn_kernel()
{
    __shared__ float Qs[64][64];   // [query][d], pre-scaled
    __shared__ float KP[64][64];   // phase 1: K^T [d][key]; phase 2: P [query][key]
    __shared__ float Vs[64][64];   // [key][d]

    const int tid = threadIdx.x;
    const int tx = tid & 15, ty = tid >> 4;
    const int bh = blockIdx.x;              // 0..31
    const int q0 = blockIdx.y * 64;

    const float* Qg = g_q + ((size_t)bh * SEQ + q0) * HDIM;
    const float* Kg = g_k + (size_t)bh * SEQ * HDIM;
    const float* Vg = g_v + (size_t)bh * SEQ * HDIM;

    // Load + pre-scale Q tile (contiguous 64x64 copy)
    for (int i = tid; i < 64*64/4; i += 256) {
        float4 qv = *(const float4*)(Qg + i*4);
        qv.x *= SCALE; qv.y *= SCALE; qv.z *= SCALE; qv.w *= SCALE;
        *(float4*)((float*)Qs + i*4) = qv;
    }

    float o[4][4];
    float mi[4], li[4];
#pragma unroll
    for (int i = 0; i < 4; i++) {
        mi[i] = -1e30f; li[i] = 0.f;
#pragma unroll
        for (int j = 0; j < 4; j++) o[i][j] = 0.f;
    }

    for (int kt = 0; kt < SEQ/64; kt++) {
        const float* Kt = Kg + (size_t)kt * 64 * HDIM;
        const float* Vt = Vg + (size_t)kt * 64 * HDIM;

        __syncthreads();   // prior iteration done reading KP(P)/Vs; Q loaded (first iter)
        // Load K transposed into KP[d][key], V natural into Vs[key][d]
        for (int i = tid; i < 1024; i += 256) {
            const int r  = i >> 4;         // key row 0..63
            const int c4 = (i & 15) << 2;  // d 0..60
            float4 kv = *(const float4*)(Kt + r*HDIM + c4);
            KP[c4+0][r] = kv.x; KP[c4+1][r] = kv.y; KP[c4+2][r] = kv.z; KP[c4+3][r] = kv.w;
            *(float4*)&Vs[r][c4] = *(const float4*)(Vt + r*HDIM + c4);
        }
        __syncthreads();

        // S = Q K^T (pre-scaled): 4x4 fragment per thread
        float s[4][4];
#pragma unroll
        for (int i = 0; i < 4; i++)
#pragma unroll
            for (int j = 0; j < 4; j++) s[i][j] = 0.f;

#pragma unroll
        for (int k4 = 0; k4 < 16; k4++) {
            float4 kv0 = *(float4*)&KP[k4*4+0][tx*4];
            float4 kv1 = *(float4*)&KP[k4*4+1][tx*4];
            float4 kv2 = *(float4*)&KP[k4*4+2][tx*4];
            float4 kv3 = *(float4*)&KP[k4*4+3][tx*4];
#pragma unroll
            for (int i = 0; i < 4; i++) {
                float4 qv = *(float4*)&Qs[ty*4+i][k4*4];
                s[i][0] += qv.x*kv0.x + qv.y*kv1.x + qv.z*kv2.x + qv.w*kv3.x;
                s[i][1] += qv.x*kv0.y + qv.y*kv1.y + qv.z*kv2.y + qv.w*kv3.y;
                s[i][2] += qv.x*kv0.z + qv.y*kv1.z + qv.z*kv2.z + qv.w*kv3.z;
                s[i][3] += qv.x*kv0.w + qv.y*kv1.w + qv.z*kv2.w + qv.w*kv3.w;
            }
        }

        // Online softmax update (reduce across the 16 tx lanes of each row)
#pragma unroll
        for (int i = 0; i < 4; i++) {
            float rm = fmaxf(fmaxf(s[i][0], s[i][1]), fmaxf(s[i][2], s[i][3]));
#pragma unroll
            for (int off = 1; off < 16; off <<= 1)
                rm = fmaxf(rm, __shfl_xor_sync(0xffffffffu, rm, off));
            const float m2 = fmaxf(mi[i], rm);
            const float alpha = __expf(mi[i] - m2);
            float rsum = 0.f;
#pragma unroll
            for (int j = 0; j < 4; j++) {
                const float p = __expf(s[i][j] - m2);
                s[i][j] = p;
                rsum += p;
            }
#pragma unroll
            for (int off = 1; off < 16; off <<= 1)
                rsum += __shfl_xor_sync(0xffffffffu, rsum, off);
            li[i] = li[i] * alpha + rsum;
            mi[i] = m2;
#pragma unroll
            for (int j = 0; j < 4; j++) o[i][j] *= alpha;
        }

        __syncthreads();   // all reads of KP (K^T) done
        // Write P into KP[query][key]
#pragma unroll
        for (int i = 0; i < 4; i++) {
            float4 pv = make_float4(s[i][0], s[i][1], s[i][2], s[i][3]);
            *(float4*)&KP[ty*4+i][tx*4] = pv;
        }
        __syncthreads();

        // O += P @ V
#pragma unroll
        for (int j4 = 0; j4 < 16; j4++) {
            float4 vv0 = *(float4*)&Vs[j4*4+0][tx*4];
            float4 vv1 = *(float4*)&Vs[j4*4+1][tx*4];
            float4 vv2 = *(float4*)&Vs[j4*4+2][tx*4];
            float4 vv3 = *(float4*)&Vs[j4*4+3][tx*4];
#pragma unroll
            for (int i = 0; i < 4; i++) {
                float4 pv = *(float4*)&KP[ty*4+i][j4*4];
                o[i][0] += pv.x*vv0.x + pv.y*vv1.x + pv.z*vv2.x + pv.w*vv3.x;
                o[i][1] += pv.x*vv0.y + pv.y*vv1.y + pv.z*vv2.y + pv.w*vv3.y;
                o[i][2] += pv.x*vv0.z + pv.y*vv1.z + pv.z*vv2.z + pv.w*vv3.z;
                o[i][3] += pv.x*vv0.w + pv.y*vv1.w + pv.z*vv2.w + pv.w*vv3.w;
            }
        }
    }

    // Normalize and write context in [B, N, H*D] layout for GEMM2
    const int b = bh >> 4, h = bh & 15;
#pragma unroll
    for (int i = 0; i < 4; i++) {
        const float inv = 1.f / li[i];
        float4 ov = make_float4(o[i][0]*inv, o[i][1]*inv, o[i][2]*inv, o[i][3]*inv);
        const size_t row = (size_t)b * SEQ + q0 + ty*4 + i;
        *(float4*)(g_ctx + row * EMB + h * HDIM + tx*4) = ov;
    }
}

// ---------------------------------------------------------------------------
extern "C" void kernel_launch(void* const* d_in, const int* in_sizes, int n_in,
                              void* d_out, int out_size)
{
    const float* x     = (const float*)d_in[0];
    const float* w_qkv = (const float*)d_in[1];
    const float* b_qkv = (const float*)d_in[2];
    const float* w_out = (const float*)d_in[3];
    const float* b_out = (const float*)d_in[4];
    float* out = (float*)d_out;

    gemm_qkv_kernel<<<dim3(3*EMB/128, MTOT/128), 256>>>(x, w_qkv, b_qkv);
    attn_kernel<<<dim3(BATCH*HEADS, SEQ/64), 256>>>();
    gemm_out_kernel<<<dim3(EMB/128, MTOT/128), 256>>>(w_out, b_out, out);
}

// round 7
// speedup vs baseline: 1.3721x; 1.3721x over previous
#include <cuda_runtime.h>
#include <cuda_bf16.h>
#include <cstdint>

#define BATCH   2
#define SEQ     2048
#define EMB     1024
#define HEADS   16
#define HDIM    64
#define MTOT    (BATCH*SEQ)        // 4096
#define SCALE   0.125f

// ---------------- scratch (device globals; cudaMalloc forbidden) -----------
__device__ float g_q[BATCH*HEADS*SEQ*HDIM];
__device__ float g_k[BATCH*HEADS*SEQ*HDIM];
__device__ float g_v[BATCH*HEADS*SEQ*HDIM];
__device__ __nv_bfloat16 g_x_hi[MTOT*EMB],   g_x_lo[MTOT*EMB];
__device__ __nv_bfloat16 g_wq_hi[3*EMB*EMB], g_wq_lo[3*EMB*EMB];
__device__ __nv_bfloat16 g_wo_hi[EMB*EMB],   g_wo_lo[EMB*EMB];
__device__ __nv_bfloat16 g_cx_hi[MTOT*EMB],  g_cx_lo[MTOT*EMB];

// ---------------- helpers --------------------------------------------------
__device__ __forceinline__ uint32_t smem_u32(const void* p) {
    uint32_t a;
    asm("{ .reg .u64 t; cvta.to.shared.u64 t, %1; cvt.u32.u64 %0, t; }"
        : "=r"(a) : "l"(p));
    return a;
}

// SW128 swizzle (Swizzle<3,4,3>): conflict-free ldmatrix on 128B rows
#define SW(off) ((uint32_t)(off) ^ ((((uint32_t)(off)) >> 3) & 0x70))

__device__ __forceinline__ void ldsm_x4(uint32_t& r0, uint32_t& r1,
                                        uint32_t& r2, uint32_t& r3, uint32_t addr) {
    asm volatile("ldmatrix.sync.aligned.m8n8.x4.shared.b16 {%0,%1,%2,%3}, [%4];"
                 : "=r"(r0), "=r"(r1), "=r"(r2), "=r"(r3) : "r"(addr));
}

__device__ __forceinline__ void mma16816(float c[4],
                                         uint32_t a0, uint32_t a1, uint32_t a2, uint32_t a3,
                                         uint32_t b0, uint32_t b1) {
    asm volatile("mma.sync.aligned.m16n8k16.row.col.f32.bf16.bf16.f32 "
                 "{%0,%1,%2,%3}, {%4,%5,%6,%7}, {%8,%9}, {%0,%1,%2,%3};"
                 : "+f"(c[0]), "+f"(c[1]), "+f"(c[2]), "+f"(c[3])
                 : "r"(a0), "r"(a1), "r"(a2), "r"(a3), "r"(b0), "r"(b1));
}

// ---------------------------------------------------------------------------
// Split fp32 -> bf16 hi/lo into device-global pairs (which: 0=x, 1=w_qkv, 2=w_out)
// ---------------------------------------------------------------------------
__global__ __launch_bounds__(256) void split_kernel(
    const float* __restrict__ in, int n4, int which)
{
    int i = blockIdx.x * 256 + threadIdx.x;
    if (i >= n4) return;
    __nv_bfloat16 *hi, *lo;
    if (which == 0)      { hi = g_x_hi;  lo = g_x_lo;  }
    else if (which == 1) { hi = g_wq_hi; lo = g_wq_lo; }
    else                 { hi = g_wo_hi; lo = g_wo_lo; }

    float4 v = ((const float4*)in)[i];
    __nv_bfloat16 h0 = __float2bfloat16(v.x);
    __nv_bfloat16 h1 = __float2bfloat16(v.y);
    __nv_bfloat16 h2 = __float2bfloat16(v.z);
    __nv_bfloat16 h3 = __float2bfloat16(v.w);
    __nv_bfloat16 l0 = __float2bfloat16(v.x - __bfloat162float(h0));
    __nv_bfloat16 l1 = __float2bfloat16(v.y - __bfloat162float(h1));
    __nv_bfloat16 l2 = __float2bfloat16(v.z - __bfloat162float(h2));
    __nv_bfloat16 l3 = __float2bfloat16(v.w - __bfloat162float(h3));
    uint2 ph, pl;
    ph.x = (uint32_t)__bfloat16_as_ushort(h0) | ((uint32_t)__bfloat16_as_ushort(h1) << 16);
    ph.y = (uint32_t)__bfloat16_as_ushort(h2) | ((uint32_t)__bfloat16_as_ushort(h3) << 16);
    pl.x = (uint32_t)__bfloat16_as_ushort(l0) | ((uint32_t)__bfloat16_as_ushort(l1) << 16);
    pl.y = (uint32_t)__bfloat16_as_ushort(l2) | ((uint32_t)__bfloat16_as_ushort(l3) << 16);
    ((uint2*)hi)[i] = ph;
    ((uint2*)lo)[i] = pl;
}

// ---------------------------------------------------------------------------
// HMMA split-bf16 GEMM: D[M,N] = A[M,K] * B[N,K]^T + bias   (K = 1024)
// 128x128 CTA tile, 8 warps in 2x4 (64x32 per warp), K-chunks of 64 bf16.
// mode 0: A=g_x, B=g_wq, scatter into g_q/g_k/g_v
// mode 1: A=g_cx, B=g_wo, write `out` row-major
// Smem: Ah@0, Al@16K, Bh@32K, Bl@48K  (each 128 rows x 128B, SW128)
// ---------------------------------------------------------------------------
#define GEMM_SMEM 65536

__global__ __launch_bounds__(256) void tc_gemm(
    const float* __restrict__ bias, float* __restrict__ out, int mode)
{
    extern __shared__ char sb[];
    const uint32_t sbu = smem_u32(sb);

    const int tid = threadIdx.x;
    const int wid = tid >> 5, lane = tid & 31;
    const int wm = wid >> 2;          // 0..1 : 64-row slab
    const int wn = wid & 3;           // 0..3 : 32-col slab
    const int m0 = blockIdx.y * 128, n0 = blockIdx.x * 128;

    const __nv_bfloat16 *Ahg, *Alg, *Bhg, *Blg;
    if (mode == 0) {
        Ahg = g_x_hi  + (size_t)m0 * EMB;  Alg = g_x_lo  + (size_t)m0 * EMB;
        Bhg = g_wq_hi + (size_t)n0 * EMB;  Blg = g_wq_lo + (size_t)n0 * EMB;
    } else {
        Ahg = g_cx_hi + (size_t)m0 * EMB;  Alg = g_cx_lo + (size_t)m0 * EMB;
        Bhg = g_wo_hi + (size_t)n0 * EMB;  Blg = g_wo_lo + (size_t)n0 * EMB;
    }

    float acc[4][4][4];               // [mt 16-row][nt 8-col][frag]
#pragma unroll
    for (int i = 0; i < 4; i++)
#pragma unroll
        for (int j = 0; j < 4; j++)
#pragma unroll
            for (int e = 0; e < 4; e++) acc[i][j][e] = 0.f;

    const int lrow  = tid >> 3;           // 0..31
    const int lcolb = (tid & 7) * 16;     // byte col within 128B row
    const int lcole = (tid & 7) * 8;      // element col

    // ldmatrix lane addressing (per x4 fragment group)
    const int a_r  = (lane & 7) + ((lane >> 3) & 1) * 8;   // A: row within m16
    const int a_kb = (lane >> 4) * 16;                     // A: k-byte offset
    const int b_r  = (lane & 7) + (lane >> 4) * 8;         // B: row within n16 pair
    const int b_kb = ((lane >> 3) & 1) * 16;               // B: k-byte offset

    for (int c = 0; c < 16; c++) {
        const int k0 = c * 64;
#pragma unroll
        for (int it = 0; it < 4; it++) {
            const int r = lrow + it * 32;
            const uint32_t sw = SW(r * 128 + lcolb);
            const size_t g = (size_t)r * EMB + k0 + lcole;
            *(float4*)(sb + 0     + sw) = *(const float4*)(Ahg + g);
            *(float4*)(sb + 16384 + sw) = *(const float4*)(Alg + g);
            *(float4*)(sb + 32768 + sw) = *(const float4*)(Bhg + g);
            *(float4*)(sb + 49152 + sw) = *(const float4*)(Blg + g);
        }
        __syncthreads();

#pragma unroll
        for (int ks = 0; ks < 4; ks++) {
            const int kb = ks * 32;
            uint32_t a[4][4], b[4][2];

            // A-hi fragments: 4 x m16 tiles
#pragma unroll
            for (int mt = 0; mt < 4; mt++) {
                const int row = wm * 64 + mt * 16 + a_r;
                ldsm_x4(a[mt][0], a[mt][1], a[mt][2], a[mt][3],
                        sbu + 0 + SW(row * 128 + kb + a_kb));
            }
            // B-hi fragments: 2 x (n16 pair) -> 4 n8 tiles
#pragma unroll
            for (int p = 0; p < 2; p++) {
                const int row = wn * 32 + p * 16 + b_r;
                uint32_t t0, t1, t2, t3;
                ldsm_x4(t0, t1, t2, t3, sbu + 32768 + SW(row * 128 + kb + b_kb));
                b[p*2][0] = t0; b[p*2][1] = t1; b[p*2+1][0] = t2; b[p*2+1][1] = t3;
            }
#pragma unroll
            for (int mt = 0; mt < 4; mt++)
#pragma unroll
                for (int nt = 0; nt < 4; nt++)
                    mma16816(acc[mt][nt], a[mt][0], a[mt][1], a[mt][2], a[mt][3],
                             b[nt][0], b[nt][1]);

            // B-lo, reuse A-hi
#pragma unroll
            for (int p = 0; p < 2; p++) {
                const int row = wn * 32 + p * 16 + b_r;
                uint32_t t0, t1, t2, t3;
                ldsm_x4(t0, t1, t2, t3, sbu + 49152 + SW(row * 128 + kb + b_kb));
                b[p*2][0] = t0; b[p*2][1] = t1; b[p*2+1][0] = t2; b[p*2+1][1] = t3;
            }
#pragma unroll
            for (int mt = 0; mt < 4; mt++)
#pragma unroll
                for (int nt = 0; nt < 4; nt++)
                    mma16816(acc[mt][nt], a[mt][0], a[mt][1], a[mt][2], a[mt][3],
                             b[nt][0], b[nt][1]);

            // A-lo x B-hi
#pragma unroll
            for (int mt = 0; mt < 4; mt++) {
                const int row = wm * 64 + mt * 16 + a_r;
                ldsm_x4(a[mt][0], a[mt][1], a[mt][2], a[mt][3],
                        sbu + 16384 + SW(row * 128 + kb + a_kb));
            }
#pragma unroll
            for (int p = 0; p < 2; p++) {
                const int row = wn * 32 + p * 16 + b_r;
                uint32_t t0, t1, t2, t3;
                ldsm_x4(t0, t1, t2, t3, sbu + 32768 + SW(row * 128 + kb + b_kb));
                b[p*2][0] = t0; b[p*2][1] = t1; b[p*2+1][0] = t2; b[p*2+1][1] = t3;
            }
#pragma unroll
            for (int mt = 0; mt < 4; mt++)
#pragma unroll
                for (int nt = 0; nt < 4; nt++)
                    mma16816(acc[mt][nt], a[mt][0], a[mt][1], a[mt][2], a[mt][3],
                             b[nt][0], b[nt][1]);
        }
        __syncthreads();
    }

    // Epilogue. acc frag mapping: c0,c1 -> row = lane>>2, cols 2*(lane&3)+{0,1};
    // c2,c3 -> row+8, same cols.
    const int rbase = m0 + wm * 64 + (lane >> 2);
    const int cbase = n0 + wn * 32 + (lane & 3) * 2;
#pragma unroll
    for (int mt = 0; mt < 4; mt++) {
#pragma unroll
        for (int nt = 0; nt < 4; nt++) {
            const int col = cbase + nt * 8;
            const float bx = bias[col], by = bias[col + 1];
#pragma unroll
            for (int half = 0; half < 2; half++) {
                const int row = rbase + mt * 16 + half * 8;
                float2 v;
                v.x = acc[mt][nt][half * 2 + 0] + bx;
                v.y = acc[mt][nt][half * 2 + 1] + by;
                if (mode == 0) {
                    const int b = row >> 11, n = row & 2047;
                    const int which = col >> 10;
                    const int hd = col & 1023;
                    const int h = hd >> 6, d = hd & 63;
                    float* dst = (which == 0) ? g_q : (which == 1) ? g_k : g_v;
                    *(float2*)&dst[((((b << 4) + h) * SEQ) + n) * HDIM + d] = v;
                } else {
                    *(float2*)(out + (size_t)row * EMB + col) = v;
                }
            }
        }
    }
}

// ---------------------------------------------------------------------------
// Flash attention (fp32 FFMA); epilogue writes bf16 hi/lo ctx for GEMM2
// ---------------------------------------------------------------------------
__global__ __launch_bounds__(256) void attn_kernel()
{
    __shared__ float Qs[64][64];
    __shared__ float KP[64][64];
    __shared__ float Vs[64][64];

    const int tid = threadIdx.x;
    const int tx = tid & 15, ty = tid >> 4;
    const int bh = blockIdx.x;
    const int q0 = blockIdx.y * 64;

    const float* Qg = g_q + ((size_t)bh * SEQ + q0) * HDIM;
    const float* Kg = g_k + (size_t)bh * SEQ * HDIM;
    const float* Vg = g_v + (size_t)bh * SEQ * HDIM;

    for (int i = tid; i < 64 * 64 / 4; i += 256) {
        float4 qv = *(const float4*)(Qg + i * 4);
        qv.x *= SCALE; qv.y *= SCALE; qv.z *= SCALE; qv.w *= SCALE;
        *(float4*)((float*)Qs + i * 4) = qv;
    }

    float o[4][4];
    float mi[4], li[4];
#pragma unroll
    for (int i = 0; i < 4; i++) {
        mi[i] = -1e30f; li[i] = 0.f;
#pragma unroll
        for (int j = 0; j < 4; j++) o[i][j] = 0.f;
    }

    for (int kt = 0; kt < SEQ / 64; kt++) {
        const float* Kt = Kg + (size_t)kt * 64 * HDIM;
        const float* Vt = Vg + (size_t)kt * 64 * HDIM;

        __syncthreads();
        for (int i = tid; i < 1024; i += 256) {
            const int r = i >> 4;
            const int c4 = (i & 15) << 2;
            float4 kv = *(const float4*)(Kt + r * HDIM + c4);
            KP[c4 + 0][r] = kv.x; KP[c4 + 1][r] = kv.y;
            KP[c4 + 2][r] = kv.z; KP[c4 + 3][r] = kv.w;
            *(float4*)&Vs[r][c4] = *(const float4*)(Vt + r * HDIM + c4);
        }
        __syncthreads();

        float s[4][4];
#pragma unroll
        for (int i = 0; i < 4; i++)
#pragma unroll
            for (int j = 0; j < 4; j++) s[i][j] = 0.f;

#pragma unroll
        for (int k4 = 0; k4 < 16; k4++) {
            float4 kv0 = *(float4*)&KP[k4 * 4 + 0][tx * 4];
            float4 kv1 = *(float4*)&KP[k4 * 4 + 1][tx * 4];
            float4 kv2 = *(float4*)&KP[k4 * 4 + 2][tx * 4];
            float4 kv3 = *(float4*)&KP[k4 * 4 + 3][tx * 4];
#pragma unroll
            for (int i = 0; i < 4; i++) {
                float4 qv = *(float4*)&Qs[ty * 4 + i][k4 * 4];
                s[i][0] += qv.x * kv0.x + qv.y * kv1.x + qv.z * kv2.x + qv.w * kv3.x;
                s[i][1] += qv.x * kv0.y + qv.y * kv1.y + qv.z * kv2.y + qv.w * kv3.y;
                s[i][2] += qv.x * kv0.z + qv.y * kv1.z + qv.z * kv2.z + qv.w * kv3.z;
                s[i][3] += qv.x * kv0.w + qv.y * kv1.w + qv.z * kv2.w + qv.w * kv3.w;
            }
        }

#pragma unroll
        for (int i = 0; i < 4; i++) {
            float rm = fmaxf(fmaxf(s[i][0], s[i][1]), fmaxf(s[i][2], s[i][3]));
#pragma unroll
            for (int off = 1; off < 16; off <<= 1)
                rm = fmaxf(rm, __shfl_xor_sync(0xffffffffu, rm, off));
            const float m2 = fmaxf(mi[i], rm);
            const float alpha = __expf(mi[i] - m2);
            float rsum = 0.f;
#pragma unroll
            for (int j = 0; j < 4; j++) {
                const float p = __expf(s[i][j] - m2);
                s[i][j] = p;
                rsum += p;
            }
#pragma unroll
            for (int off = 1; off < 16; off <<= 1)
                rsum += __shfl_xor_sync(0xffffffffu, rsum, off);
            li[i] = li[i] * alpha + rsum;
            mi[i] = m2;
#pragma unroll
            for (int j = 0; j < 4; j++) o[i][j] *= alpha;
        }

        __syncthreads();
#pragma unroll
        for (int i = 0; i < 4; i++) {
            float4 pv = make_float4(s[i][0], s[i][1], s[i][2], s[i][3]);
            *(float4*)&KP[ty * 4 + i][tx * 4] = pv;
        }
        __syncthreads();

#pragma unroll
        for (int j4 = 0; j4 < 16; j4++) {
            float4 vv0 = *(float4*)&Vs[j4 * 4 + 0][tx * 4];
            float4 vv1 = *(float4*)&Vs[j4 * 4 + 1][tx * 4];
            float4 vv2 = *(float4*)&Vs[j4 * 4 + 2][tx * 4];
            float4 vv3 = *(float4*)&Vs[j4 * 4 + 3][tx * 4];
#pragma unroll
            for (int i = 0; i < 4; i++) {
                float4 pv = *(float4*)&KP[ty * 4 + i][j4 * 4];
                o[i][0] += pv.x * vv0.x + pv.y * vv1.x + pv.z * vv2.x + pv.w * vv3.x;
                o[i][1] += pv.x * vv0.y + pv.y * vv1.y + pv.z * vv2.y + pv.w * vv3.y;
                o[i][2] += pv.x * vv0.z + pv.y * vv1.z + pv.z * vv2.z + pv.w * vv3.z;
                o[i][3] += pv.x * vv0.w + pv.y * vv1.w + pv.z * vv2.w + pv.w * vv3.w;
            }
        }
    }

    // Epilogue: normalize, split to bf16 hi/lo ctx in [B, N, H*D] layout
    const int b = bh >> 4, h = bh & 15;
#pragma unroll
    for (int i = 0; i < 4; i++) {
        const float inv = 1.f / li[i];
        const size_t rowoff = ((size_t)b * SEQ + q0 + ty * 4 + i) * EMB + h * HDIM + tx * 4;
        float v0 = o[i][0] * inv, v1 = o[i][1] * inv, v2 = o[i][2] * inv, v3 = o[i][3] * inv;
        __nv_bfloat16 h0 = __float2bfloat16(v0), h1 = __float2bfloat16(v1);
        __nv_bfloat16 h2 = __float2bfloat16(v2), h3 = __float2bfloat16(v3);
        __nv_bfloat16 l0 = __float2bfloat16(v0 - __bfloat162float(h0));
        __nv_bfloat16 l1 = __float2bfloat16(v1 - __bfloat162float(h1));
        __nv_bfloat16 l2 = __float2bfloat16(v2 - __bfloat162float(h2));
        __nv_bfloat16 l3 = __float2bfloat16(v3 - __bfloat162float(h3));
        uint2 ph, pl;
        ph.x = (uint32_t)__bfloat16_as_ushort(h0) | ((uint32_t)__bfloat16_as_ushort(h1) << 16);
        ph.y = (uint32_t)__bfloat16_as_ushort(h2) | ((uint32_t)__bfloat16_as_ushort(h3) << 16);
        pl.x = (uint32_t)__bfloat16_as_ushort(l0) | ((uint32_t)__bfloat16_as_ushort(l1) << 16);
        pl.y = (uint32_t)__bfloat16_as_ushort(l2) | ((uint32_t)__bfloat16_as_ushort(l3) << 16);
        *(uint2*)(g_cx_hi + rowoff) = ph;
        *(uint2*)(g_cx_lo + rowoff) = pl;
    }
}

// ---------------------------------------------------------------------------
extern "C" void kernel_launch(void* const* d_in, const int* in_sizes, int n_in,
                              void* d_out, int out_size)
{
    const float* x     = (const float*)d_in[0];
    const float* b_qkv = (const float*)d_in[2];
    const float* w_qkv = (const float*)d_in[1];
    const float* w_out = (const float*)d_in[3];
    const float* b_out = (const float*)d_in[4];
    float* out = (float*)d_out;

    static bool attr_set = false;
    if (!attr_set) {
        cudaFuncSetAttribute(tc_gemm, cudaFuncAttributeMaxDynamicSharedMemorySize, GEMM_SMEM);
        attr_set = true;
    }

    split_kernel<<<(MTOT*EMB/4 + 255)/256, 256>>>(x, MTOT*EMB/4, 0);
    split_kernel<<<(3*EMB*EMB/4 + 255)/256, 256>>>(w_qkv, 3*EMB*EMB/4, 1);
    split_kernel<<<(EMB*EMB/4 + 255)/256, 256>>>(w_out, EMB*EMB/4, 2);

    // GEMM1: qkv = x @ w_qkv^T + b_qkv  -> scatter into g_q/g_k/g_v
    tc_gemm<<<dim3(3*EMB/128, MTOT/128), 256, GEMM_SMEM>>>(b_qkv, nullptr, 0);

    attn_kernel<<<dim3(BATCH*HEADS, SEQ/64), 256>>>();

    // GEMM2: out = ctx @ w_out^T + b_out
    tc_gemm<<<dim3(EMB/128, MTOT/128), 256, GEMM_SMEM>>>(b_out, out, 1);
}

// round 8
// speedup vs baseline: 3.1003x; 2.2596x over previous
#include <cuda_runtime.h>
#include <cuda_bf16.h>
#include <cstdint>

#define BATCH   2
#define SEQ     2048
#define EMB     1024
#define HEADS   16
#define HDIM    64
#define MTOT    (BATCH*SEQ)        // 4096
#define BH      (BATCH*HEADS)      // 32
#define SCALE   0.125f

// ---------------- scratch (device globals; cudaMalloc forbidden) -----------
__device__ __nv_bfloat16 g_x_hi[MTOT*EMB],   g_x_lo[MTOT*EMB];
__device__ __nv_bfloat16 g_wq_hi[3*EMB*EMB], g_wq_lo[3*EMB*EMB];
__device__ __nv_bfloat16 g_wo_hi[EMB*EMB],   g_wo_lo[EMB*EMB];
__device__ __nv_bfloat16 g_cx_hi[MTOT*EMB],  g_cx_lo[MTOT*EMB];
__device__ __nv_bfloat16 g_q_hi[BH*SEQ*HDIM],  g_q_lo[BH*SEQ*HDIM];   // [bh][n][d], pre-scaled
__device__ __nv_bfloat16 g_k_hi[BH*SEQ*HDIM],  g_k_lo[BH*SEQ*HDIM];   // [bh][n][d]
__device__ __nv_bfloat16 g_vT_hi[BH*HDIM*SEQ], g_vT_lo[BH*HDIM*SEQ];  // [bh][d][n]

// ---------------- helpers --------------------------------------------------
__device__ __forceinline__ uint32_t smem_u32(const void* p) {
    uint32_t a;
    asm("{ .reg .u64 t; cvta.to.shared.u64 t, %1; cvt.u32.u64 %0, t; }"
        : "=r"(a) : "l"(p));
    return a;
}
#define SW(off) ((uint32_t)(off) ^ ((((uint32_t)(off)) >> 3) & 0x70))

__device__ __forceinline__ void ldsm_x4(uint32_t& r0, uint32_t& r1,
                                        uint32_t& r2, uint32_t& r3, uint32_t addr) {
    asm volatile("ldmatrix.sync.aligned.m8n8.x4.shared.b16 {%0,%1,%2,%3}, [%4];"
                 : "=r"(r0), "=r"(r1), "=r"(r2), "=r"(r3) : "r"(addr));
}
__device__ __forceinline__ void mma16816(float c[4],
                                         uint32_t a0, uint32_t a1, uint32_t a2, uint32_t a3,
                                         uint32_t b0, uint32_t b1) {
    asm volatile("mma.sync.aligned.m16n8k16.row.col.f32.bf16.bf16.f32 "
                 "{%0,%1,%2,%3}, {%4,%5,%6,%7}, {%8,%9}, {%0,%1,%2,%3};"
                 : "+f"(c[0]), "+f"(c[1]), "+f"(c[2]), "+f"(c[3])
                 : "r"(a0), "r"(a1), "r"(a2), "r"(a3), "r"(b0), "r"(b1));
}
__device__ __forceinline__ void cp16(uint32_t dst, const void* src) {
    asm volatile("cp.async.cg.shared.global [%0], [%1], 16;" :: "r"(dst), "l"(src));
}
#define CP_COMMIT()  asm volatile("cp.async.commit_group;" ::: "memory")
#define CP_WAIT0()   asm volatile("cp.async.wait_group 0;" ::: "memory")
#define CP_WAIT1()   asm volatile("cp.async.wait_group 1;" ::: "memory")

__device__ __forceinline__ void split_pack(float v0, float v1, uint32_t& hi, uint32_t& lo) {
    __nv_bfloat16 h0 = __float2bfloat16(v0), h1 = __float2bfloat16(v1);
    __nv_bfloat16 l0 = __float2bfloat16(v0 - __bfloat162float(h0));
    __nv_bfloat16 l1 = __float2bfloat16(v1 - __bfloat162float(h1));
    hi = (uint32_t)__bfloat16_as_ushort(h0) | ((uint32_t)__bfloat16_as_ushort(h1) << 16);
    lo = (uint32_t)__bfloat16_as_ushort(l0) | ((uint32_t)__bfloat16_as_ushort(l1) << 16);
}

// ---------------------------------------------------------------------------
// Split fp32 -> bf16 hi/lo (which: 0=x, 1=w_qkv, 2=w_out)
// ---------------------------------------------------------------------------
__global__ __launch_bounds__(256) void split_kernel(
    const float* __restrict__ in, int n4, int which)
{
    int i = blockIdx.x * 256 + threadIdx.x;
    if (i >= n4) return;
    __nv_bfloat16 *hi, *lo;
    if (which == 0)      { hi = g_x_hi;  lo = g_x_lo;  }
    else if (which == 1) { hi = g_wq_hi; lo = g_wq_lo; }
    else                 { hi = g_wo_hi; lo = g_wo_lo; }
    float4 v = ((const float4*)in)[i];
    uint32_t h01, l01, h23, l23;
    split_pack(v.x, v.y, h01, l01);
    split_pack(v.z, v.w, h23, l23);
    ((uint2*)hi)[i] = make_uint2(h01, h23);
    ((uint2*)lo)[i] = make_uint2(l01, l23);
}

// ---------------------------------------------------------------------------
// HMMA split-bf16 GEMM, cp.async double-buffered.
// D[M,N] = A[M,K]*B[N,K]^T + bias, K=1024. 128x128 CTA, 8 warps (2x4).
// Stage (64KB): Ah@0 Al@16K Bh@32K Bl@48K, two stages.
// mode 0: scatter Q(scaled)/K bf16 hi/lo + V^T bf16 hi/lo
// mode 1: fp32 out row-major
// ---------------------------------------------------------------------------
#define GSTAGE    65536
#define GEMM_SMEM 131072

__global__ __launch_bounds__(256) void tc_gemm(
    const float* __restrict__ bias, float* __restrict__ out, int mode)
{
    extern __shared__ char sb[];
    const uint32_t sbu = smem_u32(sb);
    const int tid = threadIdx.x;
    const int wid = tid >> 5, lane = tid & 31;
    const int wm = wid >> 2, wn = wid & 3;
    const int m0 = blockIdx.y * 128, n0 = blockIdx.x * 128;

    const char *Ahg, *Alg, *Bhg, *Blg;
    if (mode == 0) {
        Ahg = (const char*)(g_x_hi  + (size_t)m0 * EMB);
        Alg = (const char*)(g_x_lo  + (size_t)m0 * EMB);
        Bhg = (const char*)(g_wq_hi + (size_t)n0 * EMB);
        Blg = (const char*)(g_wq_lo + (size_t)n0 * EMB);
    } else {
        Ahg = (const char*)(g_cx_hi + (size_t)m0 * EMB);
        Alg = (const char*)(g_cx_lo + (size_t)m0 * EMB);
        Bhg = (const char*)(g_wo_hi + (size_t)n0 * EMB);
        Blg = (const char*)(g_wo_lo + (size_t)n0 * EMB);
    }

    float acc[4][4][4];
#pragma unroll
    for (int i = 0; i < 4; i++)
#pragma unroll
        for (int j = 0; j < 4; j++)
#pragma unroll
            for (int e = 0; e < 4; e++) acc[i][j][e] = 0.f;

    const int a_r  = (lane & 7) + ((lane >> 3) & 1) * 8;
    const int a_kb = (lane >> 4) * 16;
    const int b_r  = (lane & 7) + (lane >> 4) * 8;
    const int b_kb = ((lane >> 3) & 1) * 16;

    // stage loader: chunk c (64 K-cols = 128B/row), stage s
    auto load_stage = [&](int c, int s) {
        const uint32_t base = sbu + s * GSTAGE;
#pragma unroll
        for (int it = 0; it < 4; it++) {
            const int idx = tid + it * 256;
            const int r = idx >> 3, in = (idx & 7) * 16;
            const uint32_t sw = SW(r * 128 + in);
            const size_t g = (size_t)r * 2048 + (size_t)c * 128 + in;
            cp16(base + sw,          Ahg + g);
            cp16(base + 16384 + sw,  Alg + g);
            cp16(base + 32768 + sw,  Bhg + g);
            cp16(base + 49152 + sw,  Blg + g);
        }
    };

    load_stage(0, 0); CP_COMMIT();

    for (int c = 0; c < 16; c++) {
        const int buf = c & 1;
        if (c < 15) { load_stage(c + 1, buf ^ 1); CP_COMMIT(); CP_WAIT1(); }
        else        { CP_WAIT0(); }
        __syncthreads();

        const uint32_t Ah = sbu + buf * GSTAGE;
        const uint32_t Al = Ah + 16384, Bh = Ah + 32768, Bl = Ah + 49152;
#pragma unroll
        for (int ks = 0; ks < 4; ks++) {
            const int kb = ks * 32;
            uint32_t ah[4][4], al[4][4];
#pragma unroll
            for (int mt = 0; mt < 4; mt++) {
                const int row = wm * 64 + mt * 16 + a_r;
                ldsm_x4(ah[mt][0], ah[mt][1], ah[mt][2], ah[mt][3],
                        Ah + SW(row * 128 + kb + a_kb));
                ldsm_x4(al[mt][0], al[mt][1], al[mt][2], al[mt][3],
                        Al + SW(row * 128 + kb + a_kb));
            }
#pragma unroll
            for (int p = 0; p < 2; p++) {
                const int row = wn * 32 + p * 16 + b_r;
                uint32_t t0, t1, t2, t3;
                ldsm_x4(t0, t1, t2, t3, Bh + SW(row * 128 + kb + b_kb));
#pragma unroll
                for (int mt = 0; mt < 4; mt++) {
                    mma16816(acc[mt][p*2],   ah[mt][0], ah[mt][1], ah[mt][2], ah[mt][3], t0, t1);
                    mma16816(acc[mt][p*2+1], ah[mt][0], ah[mt][1], ah[mt][2], ah[mt][3], t2, t3);
                    mma16816(acc[mt][p*2],   al[mt][0], al[mt][1], al[mt][2], al[mt][3], t0, t1);
                    mma16816(acc[mt][p*2+1], al[mt][0], al[mt][1], al[mt][2], al[mt][3], t2, t3);
                }
                ldsm_x4(t0, t1, t2, t3, Bl + SW(row * 128 + kb + b_kb));
#pragma unroll
                for (int mt = 0; mt < 4; mt++) {
                    mma16816(acc[mt][p*2],   ah[mt][0], ah[mt][1], ah[mt][2], ah[mt][3], t0, t1);
                    mma16816(acc[mt][p*2+1], ah[mt][0], ah[mt][1], ah[mt][2], ah[mt][3], t2, t3);
                }
            }
        }
        __syncthreads();
    }

    const int rbase = m0 + wm * 64 + (lane >> 2);
    const int cbase = n0 + wn * 32 + (lane & 3) * 2;
#pragma unroll
    for (int mt = 0; mt < 4; mt++) {
#pragma unroll
        for (int nt = 0; nt < 4; nt++) {
            const int col = cbase + nt * 8;
            const float bx = bias[col], by = bias[col + 1];
#pragma unroll
            for (int half = 0; half < 2; half++) {
                const int row = rbase + mt * 16 + half * 8;
                float v0 = acc[mt][nt][half * 2 + 0] + bx;
                float v1 = acc[mt][nt][half * 2 + 1] + by;
                if (mode == 1) {
                    *(float2*)(out + (size_t)row * EMB + col) = make_float2(v0, v1);
                } else {
                    const int b = row >> 11, n = row & 2047;
                    const int which = col >> 10;
                    const int hd = col & 1023;
                    const int h = hd >> 6, d = hd & 63;
                    const int bhi = (b << 4) + h;
                    if (which == 0) {
                        uint32_t hi, lo;
                        split_pack(v0 * SCALE, v1 * SCALE, hi, lo);
                        const size_t off = ((size_t)bhi * SEQ + n) * HDIM + d;
                        *(uint32_t*)&g_q_hi[off] = hi;
                        *(uint32_t*)&g_q_lo[off] = lo;
                    } else if (which == 1) {
                        uint32_t hi, lo;
                        split_pack(v0, v1, hi, lo);
                        const size_t off = ((size_t)bhi * SEQ + n) * HDIM + d;
                        *(uint32_t*)&g_k_hi[off] = hi;
                        *(uint32_t*)&g_k_lo[off] = lo;
                    } else {
                        // V transposed: [bh][d][n]
                        __nv_bfloat16 h0 = __float2bfloat16(v0);
                        __nv_bfloat16 h1 = __float2bfloat16(v1);
                        __nv_bfloat16 l0 = __float2bfloat16(v0 - __bfloat162float(h0));
                        __nv_bfloat16 l1 = __float2bfloat16(v1 - __bfloat162float(h1));
                        const size_t o0 = ((size_t)bhi * HDIM + d) * SEQ + n;
                        const size_t o1 = ((size_t)bhi * HDIM + d + 1) * SEQ + n;
                        g_vT_hi[o0] = h0; g_vT_lo[o0] = l0;
                        g_vT_hi[o1] = h1; g_vT_lo[o1] = l1;
                    }
                }
            }
        }
    }
}

// ---------------------------------------------------------------------------
// HMMA flash attention, split bf16 (3-pass), cp.async double-buffered K/V.
// CTA: 128 q x 128 k per iter, 8 warps; warp owns 16 q-rows (softmax & P
// warp-private). Smem: Qh@0 Ql@16K | stage s@32K+s*64K {Kh,Kl,VTh,VTl 16K ea}
// | Ph@160K Pl@192K ([2 k-halves][128 rows][128B], SW128).  Total 224KB.
// ---------------------------------------------------------------------------
#define ASTG      65536
#define AS_KV     32768
#define AS_P      163840
#define ATTN_SMEM 229376

__global__ __launch_bounds__(256) void attn_kernel()
{
    extern __shared__ char sb[];
    const uint32_t sbu = smem_u32(sb);
    const int tid = threadIdx.x;
    const int wid = tid >> 5, lane = tid & 31;
    const int bh = blockIdx.x;
    const int q0 = blockIdx.y * 128;

    const int a_r  = (lane & 7) + ((lane >> 3) & 1) * 8;
    const int a_kb = (lane >> 4) * 16;
    const int b_r  = (lane & 7) + (lane >> 4) * 8;
    const int b_kb = ((lane >> 3) & 1) * 16;

    // ---- Q tile (contiguous 16KB each) ----
    {
        const char* qh = (const char*)(g_q_hi + ((size_t)bh * SEQ + q0) * HDIM);
        const char* ql = (const char*)(g_q_lo + ((size_t)bh * SEQ + q0) * HDIM);
#pragma unroll
        for (int it = 0; it < 4; it++) {
            const int idx = tid + it * 256;
            const int r = idx >> 3, in = (idx & 7) * 16;
            const uint32_t sw = SW(r * 128 + in);
            cp16(sbu + sw,         qh + r * 128 + in);
            cp16(sbu + 16384 + sw, ql + r * 128 + in);
        }
    }

    auto load_stage = [&](int kt, int s) {
        const uint32_t base = sbu + AS_KV + s * ASTG;
        const char* kh = (const char*)(g_k_hi + ((size_t)bh * SEQ + kt * 128) * HDIM);
        const char* kl = (const char*)(g_k_lo + ((size_t)bh * SEQ + kt * 128) * HDIM);
#pragma unroll
        for (int it = 0; it < 4; it++) {
            const int idx = tid + it * 256;
            const int r = idx >> 3, in = (idx & 7) * 16;
            const uint32_t sw = SW(r * 128 + in);
            cp16(base + sw,         kh + r * 128 + in);
            cp16(base + 16384 + sw, kl + r * 128 + in);
        }
        const char* vh = (const char*)(g_vT_hi + (size_t)bh * HDIM * SEQ) + (size_t)kt * 256;
        const char* vl = (const char*)(g_vT_lo + (size_t)bh * HDIM * SEQ) + (size_t)kt * 256;
#pragma unroll
        for (int it = 0; it < 4; it++) {
            const int idx = tid + it * 256;       // 0..1023
            const int r = idx >> 4;               // d row 0..63
            const int inner = (idx & 15) * 16;    // 0..240 within 256B row
            const int half = inner >> 7, in128 = inner & 127;
            const uint32_t dst = base + 32768 + half * 8192 + SW(r * 128 + in128);
            cp16(dst,         vh + (size_t)r * 4096 + inner);
            cp16(dst + 16384, vl + (size_t)r * 4096 + inner);
        }
    };

    load_stage(0, 0); CP_COMMIT();

    float o[8][4];
    float mi[2], li[2];
#pragma unroll
    for (int i = 0; i < 8; i++)
#pragma unroll
        for (int e = 0; e < 4; e++) o[i][e] = 0.f;
    mi[0] = mi[1] = -1e30f;
    li[0] = li[1] = 0.f;

    const int arow = wid * 16 + a_r;      // A-operand ldsm row (Q and P)

    for (int kt = 0; kt < 16; kt++) {
        const int buf = kt & 1;
        if (kt < 15) { load_stage(kt + 1, buf ^ 1); CP_COMMIT(); CP_WAIT1(); }
        else         { CP_WAIT0(); }
        __syncthreads();

        const uint32_t Kh = sbu + AS_KV + buf * ASTG;
        const uint32_t Kl = Kh + 16384;
        const uint32_t Vh = Kh + 32768;
        const uint32_t Vl = Kh + 49152;

        // ---- S = Qh*Kh + Ql*Kh + Qh*Kl ----
        float s[16][4];
#pragma unroll
        for (int i = 0; i < 16; i++)
#pragma unroll
            for (int e = 0; e < 4; e++) s[i][e] = 0.f;

#pragma unroll
        for (int ks = 0; ks < 4; ks++) {
            const int kb = ks * 32;
            uint32_t ah0, ah1, ah2, ah3, al0, al1, al2, al3;
            ldsm_x4(ah0, ah1, ah2, ah3, sbu +         SW(arow * 128 + kb + a_kb));
            ldsm_x4(al0, al1, al2, al3, sbu + 16384 + SW(arow * 128 + kb + a_kb));
#pragma unroll
            for (int p = 0; p < 8; p++) {
                const int row = p * 16 + b_r;
                uint32_t t0, t1, t2, t3;
                ldsm_x4(t0, t1, t2, t3, Kh + SW(row * 128 + kb + b_kb));
                mma16816(s[p*2],   ah0, ah1, ah2, ah3, t0, t1);
                mma16816(s[p*2+1], ah0, ah1, ah2, ah3, t2, t3);
                mma16816(s[p*2],   al0, al1, al2, al3, t0, t1);
                mma16816(s[p*2+1], al0, al1, al2, al3, t2, t3);
                ldsm_x4(t0, t1, t2, t3, Kl + SW(row * 128 + kb + b_kb));
                mma16816(s[p*2],   ah0, ah1, ah2, ah3, t0, t1);
                mma16816(s[p*2+1], ah0, ah1, ah2, ah3, t2, t3);
            }
        }

        // ---- online softmax (rows lane>>2 and lane>>2+8; reduce over quad) ----
#pragma unroll
        for (int h = 0; h < 2; h++) {
            float rm = -1e30f;
#pragma unroll
            for (int nt = 0; nt < 16; nt++)
                rm = fmaxf(rm, fmaxf(s[nt][h*2], s[nt][h*2+1]));
            rm = fmaxf(rm, __shfl_xor_sync(0xffffffffu, rm, 1));
            rm = fmaxf(rm, __shfl_xor_sync(0xffffffffu, rm, 2));
            const float m2 = fmaxf(mi[h], rm);
            const float alpha = __expf(mi[h] - m2);
            float rs = 0.f;
#pragma unroll
            for (int nt = 0; nt < 16; nt++) {
                const float p0 = __expf(s[nt][h*2]   - m2);
                const float p1 = __expf(s[nt][h*2+1] - m2);
                s[nt][h*2] = p0; s[nt][h*2+1] = p1;
                rs += p0 + p1;
            }
            rs += __shfl_xor_sync(0xffffffffu, rs, 1);
            rs += __shfl_xor_sync(0xffffffffu, rs, 2);
            li[h] = li[h] * alpha + rs;
            mi[h] = m2;
#pragma unroll
            for (int nt = 0; nt < 8; nt++) {
                o[nt][h*2]   *= alpha;
                o[nt][h*2+1] *= alpha;
            }
        }

        // ---- write P hi/lo into warp-private smem rows ----
#pragma unroll
        for (int nt = 0; nt < 16; nt++) {
            const int col = (lane & 3) * 2 + nt * 8;
            const int half = col >> 6;
            const uint32_t boff = (uint32_t)((col & 63) * 2);
#pragma unroll
            for (int h = 0; h < 2; h++) {
                const int row = wid * 16 + (lane >> 2) + h * 8;
                uint32_t hi, lo;
                split_pack(s[nt][h*2], s[nt][h*2+1], hi, lo);
                const uint32_t a = half * 16384 + SW(row * 128 + boff);
                *(uint32_t*)(sb + AS_P + a)         = hi;
                *(uint32_t*)(sb + AS_P + 32768 + a) = lo;
            }
        }
        __syncwarp();

        // ---- O += Ph*Vh + Pl*Vh + Ph*Vl ----
#pragma unroll
        for (int kb8 = 0; kb8 < 8; kb8++) {
            const int half = kb8 >> 2;
            const int koff = (kb8 & 3) * 32;
            uint32_t ah0, ah1, ah2, ah3, al0, al1, al2, al3;
            const uint32_t pa = half * 16384 + SW(arow * 128 + koff + a_kb);
            ldsm_x4(ah0, ah1, ah2, ah3, sbu + AS_P + pa);
            ldsm_x4(al0, al1, al2, al3, sbu + AS_P + 32768 + pa);
#pragma unroll
            for (int p = 0; p < 4; p++) {
                const int row = p * 16 + b_r;
                uint32_t t0, t1, t2, t3;
                const uint32_t va = half * 8192 + SW(row * 128 + koff + b_kb);
                ldsm_x4(t0, t1, t2, t3, Vh + va);
                mma16816(o[p*2],   ah0, ah1, ah2, ah3, t0, t1);
                mma16816(o[p*2+1], ah0, ah1, ah2, ah3, t2, t3);
                mma16816(o[p*2],   al0, al1, al2, al3, t0, t1);
                mma16816(o[p*2+1], al0, al1, al2, al3, t2, t3);
                ldsm_x4(t0, t1, t2, t3, Vl + va);
                mma16816(o[p*2],   ah0, ah1, ah2, ah3, t0, t1);
                mma16816(o[p*2+1], ah0, ah1, ah2, ah3, t2, t3);
            }
        }
        __syncthreads();
    }

    // ---- epilogue: normalize, split-bf16 ctx in [B,N,H*D] ----
    const int b = bh >> 4, h = bh & 15;
#pragma unroll
    for (int hh = 0; hh < 2; hh++) {
        const float inv = 1.f / li[hh];
        const int row = q0 + wid * 16 + (lane >> 2) + hh * 8;
        const size_t rbase = ((size_t)b * SEQ + row) * EMB + h * HDIM;
#pragma unroll
        for (int nt = 0; nt < 8; nt++) {
            const int col = (lane & 3) * 2 + nt * 8;
            uint32_t hi, lo;
            split_pack(o[nt][hh*2] * inv, o[nt][hh*2+1] * inv, hi, lo);
            *(uint32_t*)&g_cx_hi[rbase + col] = hi;
            *(uint32_t*)&g_cx_lo[rbase + col] = lo;
        }
    }
}

// ---------------------------------------------------------------------------
extern "C" void kernel_launch(void* const* d_in, const int* in_sizes, int n_in,
                              void* d_out, int out_size)
{
    const float* x     = (const float*)d_in[0];
    const float* w_qkv = (const float*)d_in[1];
    const float* b_qkv = (const float*)d_in[2];
    const float* w_out = (const float*)d_in[3];
    const float* b_out = (const float*)d_in[4];
    float* out = (float*)d_out;

    static bool attr_set = false;
    if (!attr_set) {
        cudaFuncSetAttribute(tc_gemm, cudaFuncAttributeMaxDynamicSharedMemorySize, GEMM_SMEM);
        cudaFuncSetAttribute(attn_kernel, cudaFuncAttributeMaxDynamicSharedMemorySize, ATTN_SMEM);
        attr_set = true;
    }

    split_kernel<<<(MTOT*EMB/4 + 255)/256, 256>>>(x, MTOT*EMB/4, 0);
    split_kernel<<<(3*EMB*EMB/4 + 255)/256, 256>>>(w_qkv, 3*EMB*EMB/4, 1);
    split_kernel<<<(EMB*EMB/4 + 255)/256, 256>>>(w_out, EMB*EMB/4, 2);

    tc_gemm<<<dim3(3*EMB/128, MTOT/128), 256, GEMM_SMEM>>>(b_qkv, nullptr, 0);
    attn_kernel<<<dim3(BH, SEQ/128), 256, ATTN_SMEM>>>();
    tc_gemm<<<dim3(EMB/128, MTOT/128), 256, GEMM_SMEM>>>(b_out, out, 1);
}

// round 9
// speedup vs baseline: 3.4586x; 1.1156x over previous
#include <cuda_runtime.h>
#include <cuda_bf16.h>
#include <cstdint>

#define BATCH   2
#define SEQ     2048
#define EMB     1024
#define HEADS   16
#define HDIM    64
#define MTOT    (BATCH*SEQ)        // 4096
#define BH      (BATCH*HEADS)      // 32
#define SCALE   0.125f

// ---------------- scratch (device globals; cudaMalloc forbidden) -----------
__device__ __nv_bfloat16 g_x_hi[MTOT*EMB],   g_x_lo[MTOT*EMB];
__device__ __nv_bfloat16 g_wq_hi[3*EMB*EMB], g_wq_lo[3*EMB*EMB];
__device__ __nv_bfloat16 g_wo_hi[EMB*EMB],   g_wo_lo[EMB*EMB];
__device__ __nv_bfloat16 g_cx_hi[MTOT*EMB],  g_cx_lo[MTOT*EMB];
__device__ __nv_bfloat16 g_q_hi[BH*SEQ*HDIM],  g_q_lo[BH*SEQ*HDIM];   // [bh][n][d], pre-scaled
__device__ __nv_bfloat16 g_k_hi[BH*SEQ*HDIM],  g_k_lo[BH*SEQ*HDIM];   // [bh][n][d]
__device__ __nv_bfloat16 g_vT_hi[BH*HDIM*SEQ], g_vT_lo[BH*HDIM*SEQ];  // [bh][d][n]

// ---------------- helpers --------------------------------------------------
__device__ __forceinline__ uint32_t smem_u32(const void* p) {
    uint32_t a;
    asm("{ .reg .u64 t; cvta.to.shared.u64 t, %1; cvt.u32.u64 %0, t; }"
        : "=r"(a) : "l"(p));
    return a;
}
#define SW(off) ((uint32_t)(off) ^ ((((uint32_t)(off)) >> 3) & 0x70))

__device__ __forceinline__ void ldsm_x4(uint32_t& r0, uint32_t& r1,
                                        uint32_t& r2, uint32_t& r3, uint32_t addr) {
    asm volatile("ldmatrix.sync.aligned.m8n8.x4.shared.b16 {%0,%1,%2,%3}, [%4];"
                 : "=r"(r0), "=r"(r1), "=r"(r2), "=r"(r3) : "r"(addr));
}
__device__ __forceinline__ void mma16816(float c[4],
                                         uint32_t a0, uint32_t a1, uint32_t a2, uint32_t a3,
                                         uint32_t b0, uint32_t b1) {
    asm volatile("mma.sync.aligned.m16n8k16.row.col.f32.bf16.bf16.f32 "
                 "{%0,%1,%2,%3}, {%4,%5,%6,%7}, {%8,%9}, {%0,%1,%2,%3};"
                 : "+f"(c[0]), "+f"(c[1]), "+f"(c[2]), "+f"(c[3])
                 : "r"(a0), "r"(a1), "r"(a2), "r"(a3), "r"(b0), "r"(b1));
}
__device__ __forceinline__ void cp16(uint32_t dst, const void* src) {
    asm volatile("cp.async.cg.shared.global [%0], [%1], 16;" :: "r"(dst), "l"(src));
}
#define CP_COMMIT()  asm volatile("cp.async.commit_group;" ::: "memory")
#define CP_WAIT0()   asm volatile("cp.async.wait_group 0;" ::: "memory")
#define CP_WAIT1()   asm volatile("cp.async.wait_group 1;" ::: "memory")
#define CP_WAIT2()   asm volatile("cp.async.wait_group 2;" ::: "memory")

__device__ __forceinline__ void split_pack(float v0, float v1, uint32_t& hi, uint32_t& lo) {
    __nv_bfloat16 h0 = __float2bfloat16(v0), h1 = __float2bfloat16(v1);
    __nv_bfloat16 l0 = __float2bfloat16(v0 - __bfloat162float(h0));
    __nv_bfloat16 l1 = __float2bfloat16(v1 - __bfloat162float(h1));
    hi = (uint32_t)__bfloat16_as_ushort(h0) | ((uint32_t)__bfloat16_as_ushort(h1) << 16);
    lo = (uint32_t)__bfloat16_as_ushort(l0) | ((uint32_t)__bfloat16_as_ushort(l1) << 16);
}

// ---------------------------------------------------------------------------
// Split fp32 -> bf16 hi/lo (which: 0=x, 1=w_qkv, 2=w_out)
// ---------------------------------------------------------------------------
__global__ __launch_bounds__(256) void split_kernel(
    const float* __restrict__ in, int n4, int which)
{
    int i = blockIdx.x * 256 + threadIdx.x;
    if (i >= n4) return;
    __nv_bfloat16 *hi, *lo;
    if (which == 0)      { hi = g_x_hi;  lo = g_x_lo;  }
    else if (which == 1) { hi = g_wq_hi; lo = g_wq_lo; }
    else                 { hi = g_wo_hi; lo = g_wo_lo; }
    float4 v = ((const float4*)in)[i];
    uint32_t h01, l01, h23, l23;
    split_pack(v.x, v.y, h01, l01);
    split_pack(v.z, v.w, h23, l23);
    ((uint2*)hi)[i] = make_uint2(h01, h23);
    ((uint2*)lo)[i] = make_uint2(l01, l23);
}

// ---------------------------------------------------------------------------
// HMMA split-bf16 GEMM, cp.async 3-stage pipeline (2-deep prefetch).
// D[M,N] = A[M,K]*B[N,K]^T + bias, K=1024. 128x128 CTA, 8 warps (2x4).
// Stage (64KB): Ah@0 Al@16K Bh@32K Bl@48K; 3 stages = 192KB.
// mode 0: scatter Q(scaled)/K bf16 hi/lo + V^T bf16 hi/lo;  mode 1: fp32 out.
// ---------------------------------------------------------------------------
#define GSTAGE    65536
#define GEMM_SMEM (3*GSTAGE)

__global__ __launch_bounds__(256) void tc_gemm(
    const float* __restrict__ bias, float* __restrict__ out, int mode)
{
    extern __shared__ char sb[];
    const uint32_t sbu = smem_u32(sb);
    const int tid = threadIdx.x;
    const int wid = tid >> 5, lane = tid & 31;
    const int wm = wid >> 2, wn = wid & 3;
    const int m0 = blockIdx.y * 128, n0 = blockIdx.x * 128;

    const char *Ahg, *Alg, *Bhg, *Blg;
    if (mode == 0) {
        Ahg = (const char*)(g_x_hi  + (size_t)m0 * EMB);
        Alg = (const char*)(g_x_lo  + (size_t)m0 * EMB);
        Bhg = (const char*)(g_wq_hi + (size_t)n0 * EMB);
        Blg = (const char*)(g_wq_lo + (size_t)n0 * EMB);
    } else {
        Ahg = (const char*)(g_cx_hi + (size_t)m0 * EMB);
        Alg = (const char*)(g_cx_lo + (size_t)m0 * EMB);
        Bhg = (const char*)(g_wo_hi + (size_t)n0 * EMB);
        Blg = (const char*)(g_wo_lo + (size_t)n0 * EMB);
    }

    float acc[4][4][4];
#pragma unroll
    for (int i = 0; i < 4; i++)
#pragma unroll
        for (int j = 0; j < 4; j++)
#pragma unroll
            for (int e = 0; e < 4; e++) acc[i][j][e] = 0.f;

    const int a_r  = (lane & 7) + ((lane >> 3) & 1) * 8;
    const int a_kb = (lane >> 4) * 16;
    const int b_r  = (lane & 7) + (lane >> 4) * 8;
    const int b_kb = ((lane >> 3) & 1) * 16;

    auto load_stage = [&](int c, int s) {
        const uint32_t base = sbu + s * GSTAGE;
#pragma unroll
        for (int it = 0; it < 4; it++) {
            const int idx = tid + it * 256;
            const int r = idx >> 3, in = (idx & 7) * 16;
            const uint32_t sw = SW(r * 128 + in);
            const size_t g = (size_t)r * 2048 + (size_t)c * 128 + in;
            cp16(base + sw,          Ahg + g);
            cp16(base + 16384 + sw,  Alg + g);
            cp16(base + 32768 + sw,  Bhg + g);
            cp16(base + 49152 + sw,  Blg + g);
        }
    };

    load_stage(0, 0); CP_COMMIT();
    load_stage(1, 1); CP_COMMIT();

    for (int c = 0; c < 16; c++) {
        const int buf = c % 3;
        if (c + 2 < 16) { load_stage(c + 2, (c + 2) % 3); CP_COMMIT(); CP_WAIT2(); }
        else if (c == 14) { CP_WAIT1(); }
        else              { CP_WAIT0(); }
        __syncthreads();

        const uint32_t Ah = sbu + buf * GSTAGE;
        const uint32_t Al = Ah + 16384, Bh = Ah + 32768, Bl = Ah + 49152;
#pragma unroll
        for (int ks = 0; ks < 4; ks++) {
            const int kb = ks * 32;
            uint32_t ah[4][4], al[4][4];
#pragma unroll
            for (int mt = 0; mt < 4; mt++) {
                const int row = wm * 64 + mt * 16 + a_r;
                ldsm_x4(ah[mt][0], ah[mt][1], ah[mt][2], ah[mt][3],
                        Ah + SW(row * 128 + kb + a_kb));
                ldsm_x4(al[mt][0], al[mt][1], al[mt][2], al[mt][3],
                        Al + SW(row * 128 + kb + a_kb));
            }
#pragma unroll
            for (int p = 0; p < 2; p++) {
                const int row = wn * 32 + p * 16 + b_r;
                uint32_t t0, t1, t2, t3;
                ldsm_x4(t0, t1, t2, t3, Bh + SW(row * 128 + kb + b_kb));
#pragma unroll
                for (int mt = 0; mt < 4; mt++) {
                    mma16816(acc[mt][p*2],   ah[mt][0], ah[mt][1], ah[mt][2], ah[mt][3], t0, t1);
                    mma16816(acc[mt][p*2+1], ah[mt][0], ah[mt][1], ah[mt][2], ah[mt][3], t2, t3);
                    mma16816(acc[mt][p*2],   al[mt][0], al[mt][1], al[mt][2], al[mt][3], t0, t1);
                    mma16816(acc[mt][p*2+1], al[mt][0], al[mt][1], al[mt][2], al[mt][3], t2, t3);
                }
                ldsm_x4(t0, t1, t2, t3, Bl + SW(row * 128 + kb + b_kb));
#pragma unroll
                for (int mt = 0; mt < 4; mt++) {
                    mma16816(acc[mt][p*2],   ah[mt][0], ah[mt][1], ah[mt][2], ah[mt][3], t0, t1);
                    mma16816(acc[mt][p*2+1], ah[mt][0], ah[mt][1], ah[mt][2], ah[mt][3], t2, t3);
                }
            }
        }
        __syncthreads();
    }

    const int rbase = m0 + wm * 64 + (lane >> 2);
    const int cbase = n0 + wn * 32 + (lane & 3) * 2;
#pragma unroll
    for (int mt = 0; mt < 4; mt++) {
#pragma unroll
        for (int nt = 0; nt < 4; nt++) {
            const int col = cbase + nt * 8;
            const float bx = bias[col], by = bias[col + 1];
#pragma unroll
            for (int half = 0; half < 2; half++) {
                const int row = rbase + mt * 16 + half * 8;
                float v0 = acc[mt][nt][half * 2 + 0] + bx;
                float v1 = acc[mt][nt][half * 2 + 1] + by;
                if (mode == 1) {
                    *(float2*)(out + (size_t)row * EMB + col) = make_float2(v0, v1);
                } else {
                    const int b = row >> 11, n = row & 2047;
                    const int which = col >> 10;
                    const int hd = col & 1023;
                    const int h = hd >> 6, d = hd & 63;
                    const int bhi = (b << 4) + h;
                    if (which == 0) {
                        uint32_t hi, lo;
                        split_pack(v0 * SCALE, v1 * SCALE, hi, lo);
                        const size_t off = ((size_t)bhi * SEQ + n) * HDIM + d;
                        *(uint32_t*)&g_q_hi[off] = hi;
                        *(uint32_t*)&g_q_lo[off] = lo;
                    } else if (which == 1) {
                        uint32_t hi, lo;
                        split_pack(v0, v1, hi, lo);
                        const size_t off = ((size_t)bhi * SEQ + n) * HDIM + d;
                        *(uint32_t*)&g_k_hi[off] = hi;
                        *(uint32_t*)&g_k_lo[off] = lo;
                    } else {
                        __nv_bfloat16 h0 = __float2bfloat16(v0);
                        __nv_bfloat16 h1 = __float2bfloat16(v1);
                        __nv_bfloat16 l0 = __float2bfloat16(v0 - __bfloat162float(h0));
                        __nv_bfloat16 l1 = __float2bfloat16(v1 - __bfloat162float(h1));
                        const size_t o0 = ((size_t)bhi * HDIM + d) * SEQ + n;
                        const size_t o1 = ((size_t)bhi * HDIM + d + 1) * SEQ + n;
                        g_vT_hi[o0] = h0; g_vT_lo[o0] = l0;
                        g_vT_hi[o1] = h1; g_vT_lo[o1] = l1;
                    }
                }
            }
        }
    }
}

// ---------------------------------------------------------------------------
// HMMA flash attention, split bf16 (3-pass). P stays in REGISTERS:
// S-accumulator frags are re-packed (bf16 hi/lo) directly as the A-operand
// of the P*V MMA (FA-2 fragment-compatibility trick) -> no P smem at all.
// Freed 64KB buys a 3-stage KV pipeline (2-deep cp.async prefetch).
// Smem: Qh@0 Ql@16K | stage s@32K+s*64K {Kh,Kl 16K ea; VT hi 2x8K; VT lo 2x8K}
// Total 224KB.
// ---------------------------------------------------------------------------
#define ASTG      65536
#define AS_KV     32768
#define ATTN_SMEM (AS_KV + 3*ASTG)

__global__ __launch_bounds__(256) void attn_kernel()
{
    extern __shared__ char sb[];
    const uint32_t sbu = smem_u32(sb);
    const int tid = threadIdx.x;
    const int wid = tid >> 5, lane = tid & 31;
    const int bh = blockIdx.x;
    const int q0 = blockIdx.y * 128;

    const int a_r  = (lane & 7) + ((lane >> 3) & 1) * 8;
    const int a_kb = (lane >> 4) * 16;
    const int b_r  = (lane & 7) + (lane >> 4) * 8;
    const int b_kb = ((lane >> 3) & 1) * 16;

    // ---- Q tile ----
    {
        const char* qh = (const char*)(g_q_hi + ((size_t)bh * SEQ + q0) * HDIM);
        const char* ql = (const char*)(g_q_lo + ((size_t)bh * SEQ + q0) * HDIM);
#pragma unroll
        for (int it = 0; it < 4; it++) {
            const int idx = tid + it * 256;
            const int r = idx >> 3, in = (idx & 7) * 16;
            const uint32_t sw = SW(r * 128 + in);
            cp16(sbu + sw,         qh + r * 128 + in);
            cp16(sbu + 16384 + sw, ql + r * 128 + in);
        }
    }

    auto load_stage = [&](int kt, int s) {
        const uint32_t base = sbu + AS_KV + s * ASTG;
        const char* kh = (const char*)(g_k_hi + ((size_t)bh * SEQ + kt * 128) * HDIM);
        const char* kl = (const char*)(g_k_lo + ((size_t)bh * SEQ + kt * 128) * HDIM);
#pragma unroll
        for (int it = 0; it < 4; it++) {
            const int idx = tid + it * 256;
            const int r = idx >> 3, in = (idx & 7) * 16;
            const uint32_t sw = SW(r * 128 + in);
            cp16(base + sw,         kh + r * 128 + in);
            cp16(base + 16384 + sw, kl + r * 128 + in);
        }
        const char* vh = (const char*)(g_vT_hi + (size_t)bh * HDIM * SEQ) + (size_t)kt * 256;
        const char* vl = (const char*)(g_vT_lo + (size_t)bh * HDIM * SEQ) + (size_t)kt * 256;
#pragma unroll
        for (int it = 0; it < 4; it++) {
            const int idx = tid + it * 256;       // 0..1023
            const int r = idx >> 4;               // d row 0..63
            const int inner = (idx & 15) * 16;    // byte within 256B row
            const int half = inner >> 7, in128 = inner & 127;
            const uint32_t dst = base + 32768 + half * 8192 + SW(r * 128 + in128);
            cp16(dst,         vh + (size_t)r * 4096 + inner);
            cp16(dst + 16384, vl + (size_t)r * 4096 + inner);
        }
    };

    load_stage(0, 0); CP_COMMIT();
    load_stage(1, 1); CP_COMMIT();

    float o[8][4];
    float mi[2], li[2];
#pragma unroll
    for (int i = 0; i < 8; i++)
#pragma unroll
        for (int e = 0; e < 4; e++) o[i][e] = 0.f;
    mi[0] = mi[1] = -1e30f;
    li[0] = li[1] = 0.f;

    const int arow = wid * 16 + a_r;

    for (int kt = 0; kt < 16; kt++) {
        const int buf = kt % 3;
        if (kt + 2 < 16) { load_stage(kt + 2, (kt + 2) % 3); CP_COMMIT(); CP_WAIT2(); }
        else if (kt == 14) { CP_WAIT1(); }
        else               { CP_WAIT0(); }
        __syncthreads();

        const uint32_t Kh = sbu + AS_KV + buf * ASTG;
        const uint32_t Kl = Kh + 16384;
        const uint32_t Vh = Kh + 32768;
        const uint32_t Vl = Kh + 49152;

        // ---- S = Qh*Kh + Ql*Kh + Qh*Kl ----
        float s[16][4];
#pragma unroll
        for (int i = 0; i < 16; i++)
#pragma unroll
            for (int e = 0; e < 4; e++) s[i][e] = 0.f;

#pragma unroll
        for (int ks = 0; ks < 4; ks++) {
            const int kb = ks * 32;
            uint32_t ah0, ah1, ah2, ah3, al0, al1, al2, al3;
            ldsm_x4(ah0, ah1, ah2, ah3, sbu +         SW(arow * 128 + kb + a_kb));
            ldsm_x4(al0, al1, al2, al3, sbu + 16384 + SW(arow * 128 + kb + a_kb));
#pragma unroll
            for (int p = 0; p < 8; p++) {
                const int row = p * 16 + b_r;
                uint32_t t0, t1, t2, t3;
                ldsm_x4(t0, t1, t2, t3, Kh + SW(row * 128 + kb + b_kb));
                mma16816(s[p*2],   ah0, ah1, ah2, ah3, t0, t1);
                mma16816(s[p*2+1], ah0, ah1, ah2, ah3, t2, t3);
                mma16816(s[p*2],   al0, al1, al2, al3, t0, t1);
                mma16816(s[p*2+1], al0, al1, al2, al3, t2, t3);
                ldsm_x4(t0, t1, t2, t3, Kl + SW(row * 128 + kb + b_kb));
                mma16816(s[p*2],   ah0, ah1, ah2, ah3, t0, t1);
                mma16816(s[p*2+1], ah0, ah1, ah2, ah3, t2, t3);
            }
        }

        // ---- online softmax (rows lane>>2, lane>>2+8; quad reduce) ----
#pragma unroll
        for (int h = 0; h < 2; h++) {
            float rm = -1e30f;
#pragma unroll
            for (int nt = 0; nt < 16; nt++)
                rm = fmaxf(rm, fmaxf(s[nt][h*2], s[nt][h*2+1]));
            rm = fmaxf(rm, __shfl_xor_sync(0xffffffffu, rm, 1));
            rm = fmaxf(rm, __shfl_xor_sync(0xffffffffu, rm, 2));
            const float m2 = fmaxf(mi[h], rm);
            const float alpha = __expf(mi[h] - m2);
            float rs = 0.f;
#pragma unroll
            for (int nt = 0; nt < 16; nt++) {
                const float p0 = __expf(s[nt][h*2]   - m2);
                const float p1 = __expf(s[nt][h*2+1] - m2);
                s[nt][h*2] = p0; s[nt][h*2+1] = p1;
                rs += p0 + p1;
            }
            rs += __shfl_xor_sync(0xffffffffu, rs, 1);
            rs += __shfl_xor_sync(0xffffffffu, rs, 2);
            li[h] = li[h] * alpha + rs;
            mi[h] = m2;
#pragma unroll
            for (int nt = 0; nt < 8; nt++) {
                o[nt][h*2]   *= alpha;
                o[nt][h*2+1] *= alpha;
            }
        }

        // ---- O += Ph*Vh + Pl*Vh + Ph*Vl, P fed straight from registers ----
#pragma unroll
        for (int kc = 0; kc < 8; kc++) {
            const int half = kc >> 2;
            const int koff = (kc & 3) * 32;
            uint32_t ah0, ah1, ah2, ah3, al0, al1, al2, al3;
            split_pack(s[2*kc][0],   s[2*kc][1],   ah0, al0);
            split_pack(s[2*kc][2],   s[2*kc][3],   ah1, al1);
            split_pack(s[2*kc+1][0], s[2*kc+1][1], ah2, al2);
            split_pack(s[2*kc+1][2], s[2*kc+1][3], ah3, al3);
#pragma unroll
            for (int p = 0; p < 4; p++) {
                const int row = p * 16 + b_r;
                uint32_t t0, t1, t2, t3;
                const uint32_t va = half * 8192 + SW(row * 128 + koff + b_kb);
                ldsm_x4(t0, t1, t2, t3, Vh + va);
                mma16816(o[p*2],   ah0, ah1, ah2, ah3, t0, t1);
                mma16816(o[p*2+1], ah0, ah1, ah2, ah3, t2, t3);
                mma16816(o[p*2],   al0, al1, al2, al3, t0, t1);
                mma16816(o[p*2+1], al0, al1, al2, al3, t2, t3);
                ldsm_x4(t0, t1, t2, t3, Vl + va);
                mma16816(o[p*2],   ah0, ah1, ah2, ah3, t0, t1);
                mma16816(o[p*2+1], ah0, ah1, ah2, ah3, t2, t3);
            }
        }
        __syncthreads();
    }

    // ---- epilogue: normalize, split-bf16 ctx in [B,N,H*D] ----
    const int b = bh >> 4, h = bh & 15;
#pragma unroll
    for (int hh = 0; hh < 2; hh++) {
        const float inv = 1.f / li[hh];
        const int row = q0 + wid * 16 + (lane >> 2) + hh * 8;
        const size_t rbase = ((size_t)b * SEQ + row) * EMB + h * HDIM;
#pragma unroll
        for (int nt = 0; nt < 8; nt++) {
            const int col = (lane & 3) * 2 + nt * 8;
            uint32_t hi, lo;
            split_pack(o[nt][hh*2] * inv, o[nt][hh*2+1] * inv, hi, lo);
            *(uint32_t*)&g_cx_hi[rbase + col] = hi;
            *(uint32_t*)&g_cx_lo[rbase + col] = lo;
        }
    }
}

// ---------------------------------------------------------------------------
extern "C" void kernel_launch(void* const* d_in, const int* in_sizes, int n_in,
                              void* d_out, int out_size)
{
    const float* x     = (const float*)d_in[0];
    const float* w_qkv = (const float*)d_in[1];
    const float* b_qkv = (const float*)d_in[2];
    const float* w_out = (const float*)d_in[3];
    const float* b_out = (const float*)d_in[4];
    float* out = (float*)d_out;

    static bool attr_set = false;
    if (!attr_set) {
        cudaFuncSetAttribute(tc_gemm, cudaFuncAttributeMaxDynamicSharedMemorySize, GEMM_SMEM);
        cudaFuncSetAttribute(attn_kernel, cudaFuncAttributeMaxDynamicSharedMemorySize, ATTN_SMEM);
        attr_set = true;
    }

    split_kernel<<<(MTOT*EMB/4 + 255)/256, 256>>>(x, MTOT*EMB/4, 0);
    split_kernel<<<(3*EMB*EMB/4 + 255)/256, 256>>>(w_qkv, 3*EMB*EMB/4, 1);
    split_kernel<<<(EMB*EMB/4 + 255)/256, 256>>>(w_out, EMB*EMB/4, 2);

    tc_gemm<<<dim3(3*EMB/128, MTOT/128), 256, GEMM_SMEM>>>(b_qkv, nullptr, 0);
    attn_kernel<<<dim3(BH, SEQ/128), 256, ATTN_SMEM>>>();
    tc_gemm<<<dim3(EMB/128, MTOT/128), 256, GEMM_SMEM>>>(b_out, out, 1);
}